// round 14
// baseline (speedup 1.0000x reference)
#include <cuda_runtime.h>
#include <math.h>

#define NN 16384
#define NG 256
#define KK 50
#define NB 5
#define MAXC 192     // hard cap; counting fallback handles (128, 192]
#define WARPS 8
#define SPLIT 16
#define BIGD 1e10f

__device__ int g_bounds[NG + 1];   // lower_bound(batch, g) for g in [0, NG]

__device__ __forceinline__ float ex2_approx(float x) {
    float r; asm("ex2.approx.f32 %0, %1;" : "=f"(r) : "f"(x)); return r;
}
__device__ __forceinline__ float sqrt_approx(float x) {
    float r; asm("sqrt.approx.f32 %0, %1;" : "=f"(r) : "f"(x)); return r;
}

// one bitonic compare-exchange step (cross-lane, distance d)
__device__ __forceinline__ unsigned cmpex(unsigned k, int d, bool keep_min) {
    unsigned o = __shfl_xor_sync(0xFFFFFFFFu, k, d);
    unsigned mn = min(k, o), mx = max(k, o);
    return keep_min ? mn : mx;
}

// ---- kernel 1: graph boundaries via change-scan; smem shares neighbor value ----
__global__ void bounds_kernel(const int* __restrict__ batch_w) {
    __shared__ int sv[257];
    const bool is64 = (batch_w[NN - 1] == 0);   // int64 layout: high word at odd index
    const int i = blockIdx.x * 256 + threadIdx.x;
    const int v = batch_w[is64 ? 2 * i : i];
    sv[threadIdx.x + 1] = v;
    if (threadIdx.x == 0)
        sv[0] = (i == 0) ? -1 : batch_w[is64 ? 2 * (i - 1) : (i - 1)];
    __syncthreads();
    const int prev = sv[threadIdx.x];
    // lower_bound(batch, g) == i exactly for g in (prev, v]
    for (int gg = prev + 1; gg <= v; ++gg) g_bounds[gg] = i;
    if (i == NN - 1)
        for (int gg = v + 1; gg <= NG; ++gg) g_bounds[gg] = NN;
}

// Output layout (float32, out_size = 8*N*K):
//   [0,      nK)  : edge_index row 0 (src)
//   [nK,    2nK)  : edge_index row 1 (dst)
//   [2nK,   3nK)  : dist
//   [3nK,   8nK)  : rdf [nK,5] row-major
__global__ __launch_bounds__(256, 8) void knn_rdf_kernel(
    const float* __restrict__ pos,
    float*       __restrict__ out)
{
    __shared__ float4 p4[MAXC];                           // {x, y, z, |p|^2}
    __shared__ __align__(16) unsigned keys[WARPS][MAXC];  // fallback (cnt>128) only
    __shared__ unsigned slotK[WARPS][KK];                 // fallback only

    const int g   = blockIdx.x;
    const int tid = threadIdx.x;

    const int start = g_bounds[g];
    const int end   = g_bounds[g + 1];
    int cnt = end - start;
    if (cnt <= 0) return;
    if (cnt > MAXC) cnt = MAXC;   // safety clamp (never expected)
    // whole-block early exit: this block's warps own nodes [8*y, 8*y+8) (+ fallback strides)
    if (cnt <= 128 && WARPS * blockIdx.y >= cnt) return;
    const int cntR = (cnt + 3) & ~3;

    // stage this graph's positions + squared norms as float4
    for (int j = tid; j < cnt; j += blockDim.x) {
        float x = pos[3 * (start + j) + 0];
        float y = pos[3 * (start + j) + 1];
        float z = pos[3 * (start + j) + 2];
        p4[j] = make_float4(x, y, z, x * x + y * y + z * z);
    }
    __syncthreads();

    const int warp = tid >> 5, lane = tid & 31;
    const unsigned nK = (unsigned)NN * KK;     // 819200, fits 32-bit
    const float EA = -0.11541560327111707f;    // -0.08 * log2(e)
    const float ET =  0.57707801635558534f;    //  0.40 * log2(e)
    const float C1 = 0.60653065971263342360f;
    const float C2 = 0.13533528323661270231f;
    const float C3 = 0.01110899653824230650f;
    const float C4 = 3.35462627902511838821e-4f;
    const float padDist = sqrtf(BIGD);

    const int v = min(cnt - 1, KK);            // valid (non-padding) slots per node

    // emit slot s using per-node precomputed pointers (p0..pr, ig, figf)
    auto emit_slot = [&](float* p0, float* p1, float* p2, float* pr,
                         int ig, float figf, int s, unsigned key) {
        float fsrc, dist, r0, r1, r2, r3, r4;
        if (s < v) {
            const int j = (int)(key & 0xFFu);
            unsigned ub = (key & 0xFFFFFF00u) | 0x80u;      // midpoint-restore low bits
            unsigned bits = (ub & 0x80000000u) ? (ub ^ 0x80000000u) : ~ub;
            const float d2 = __uint_as_float(bits);
            fsrc = (float)(start + j);
            dist = sqrt_approx(fmaxf(d2, 1e-12f));
            float A = ex2_approx(EA * dist * dist);
            float t = ex2_approx(ET * dist);
            r0 = A;
            float p = A * t; r1 = p * C1;
            p *= t;          r2 = p * C2;
            p *= t;          r3 = p * C3;
            p *= t;          r4 = p * C4;
        } else {
            int m = s - v;   // padding: masked indices ascending {0..start-1} ∪ {ig} ∪ {end..}
            int pidx = (m < start) ? m : ((m == start) ? ig : end + (m - start - 1));
            fsrc = (float)pidx;
            dist = padDist;
            r0 = r1 = r2 = r3 = r4 = 0.0f;
        }
        p0[s] = fsrc;
        p1[s] = figf;
        p2[s] = dist;
        float* rp = pr + 5 * s;
        rp[0] = r0; rp[1] = r1; rp[2] = r2; rp[3] = r3; rp[4] = r4;
    };

    // key from precomputed node record pi (one LDS.128 per candidate)
    auto makekey = [&](const float4 pi, int i, int j) -> unsigned {
        unsigned key = 0xFFFFFFFFu;
        if (j < cnt && j != i) {
            const float4 pj = p4[j];
            float d2 = pi.w + pj.w - 2.0f * (pi.x * pj.x + pi.y * pj.y + pi.z * pj.z);
            unsigned ub = __float_as_uint(d2);
            ub ^= ((unsigned)((int)ub >> 31)) | 0x80000000u;   // monotonic float->uint
            key = (ub & 0xFFFFFF00u) | (unsigned)j;
        }
        return key;
    };

    if (cnt <= 64) {
        // ---------- fast path A: 64-key register bitonic sort, one node per warp ----------
        const int i = warp + WARPS * blockIdx.y;
        if (i >= cnt) return;
        const float4 pi = p4[i];

        unsigned k0 = makekey(pi, i, lane);
        unsigned k1 = makekey(pi, i, lane + 32);

        #pragma unroll
        for (int s = 2; s <= 16; s <<= 1) {
            #pragma unroll
            for (int d = s >> 1; d >= 1; d >>= 1) {
                bool km = ((lane & d) == 0) == ((lane & s) == 0);
                k0 = cmpex(k0, d, km);
                k1 = cmpex(k1, d, km);
            }
        }
        #pragma unroll
        for (int d = 16; d >= 1; d >>= 1) {       // stage s=32
            bool pm = ((lane & d) == 0);
            k0 = cmpex(k0, d, pm);
            k1 = cmpex(k1, d, !pm);
        }
        { unsigned a = min(k0, k1), b = max(k0, k1); k0 = a; k1 = b; }  // s=64, d=32
        #pragma unroll
        for (int d = 16; d >= 1; d >>= 1) {
            bool pm = ((lane & d) == 0);
            k0 = cmpex(k0, d, pm);
            k1 = cmpex(k1, d, pm);
        }

        // per-node emit state computed once
        const int ig = start + i;
        const unsigned eb = (unsigned)ig * KK;
        float* p0 = out + eb;
        float* p1 = p0 + nK;
        float* p2 = p1 + nK;
        float* pr = out + 3u * nK + 5u * eb;
        const float figf = (float)ig;

        emit_slot(p0, p1, p2, pr, ig, figf, lane, k0);
        if (lane < KK - 32) emit_slot(p0, p1, p2, pr, ig, figf, lane + 32, k1);
    } else if (cnt <= 128) {
        // ---------- fast path B: bitonic top-64 of 128 keys, ONE node per warp ----------
        const int i = warp + WARPS * blockIdx.y;   // SPLIT=16 -> i in [0,128)
        if (i >= cnt) return;
        const float4 pi = p4[i];

        unsigned k0 = makekey(pi, i, lane);
        unsigned k1 = makekey(pi, i, lane + 32);
        unsigned k2 = makekey(pi, i, lane + 64);
        unsigned k3 = makekey(pi, i, lane + 96);

        // stages s=2..16: cross-lane, same predicate all regs
        #pragma unroll
        for (int s = 2; s <= 16; s <<= 1) {
            #pragma unroll
            for (int d = s >> 1; d >= 1; d >>= 1) {
                bool km = ((lane & d) == 0) == ((lane & s) == 0);
                k0 = cmpex(k0, d, km);
                k1 = cmpex(k1, d, km);
                k2 = cmpex(k2, d, km);
                k3 = cmpex(k3, d, km);
            }
        }
        // stage s=32
        #pragma unroll
        for (int d = 16; d >= 1; d >>= 1) {
            bool pm = ((lane & d) == 0);
            k0 = cmpex(k0, d, pm);
            k1 = cmpex(k1, d, !pm);
            k2 = cmpex(k2, d, pm);
            k3 = cmpex(k3, d, !pm);
        }
        // stage s=64: (k0,k1) ascending 64-sort, (k2,k3) descending 64-sort
        { unsigned a = min(k0, k1), b = max(k0, k1); k0 = a; k1 = b; }
        { unsigned a = max(k2, k3), b = min(k2, k3); k2 = a; k3 = b; }
        #pragma unroll
        for (int d = 16; d >= 1; d >>= 1) {
            bool pm = ((lane & d) == 0);
            k0 = cmpex(k0, d, pm);
            k1 = cmpex(k1, d, pm);
            k2 = cmpex(k2, d, !pm);
            k3 = cmpex(k3, d, !pm);
        }
        // top-64 min-merge + 64-wide bitonic merge of (k0,k1)
        k0 = min(k0, k2);
        k1 = min(k1, k3);
        { unsigned a = min(k0, k1), b = max(k0, k1); k0 = a; k1 = b; }
        #pragma unroll
        for (int d = 16; d >= 1; d >>= 1) {
            bool pm = ((lane & d) == 0);
            k0 = cmpex(k0, d, pm);
            k1 = cmpex(k1, d, pm);
        }

        const int ig = start + i;
        const unsigned eb = (unsigned)ig * KK;
        float* p0 = out + eb;
        float* p1 = p0 + nK;
        float* p2 = p1 + nK;
        float* pr = out + 3u * nK + 5u * eb;
        const float figf = (float)ig;

        emit_slot(p0, p1, p2, pr, ig, figf, lane, k0);
        if (lane < KK - 32) emit_slot(p0, p1, p2, pr, ig, figf, lane + 32, k1);
    } else {
        // ---------- fallback (cnt>128, ~never): counting rank via smem keys ----------
        unsigned* kw = keys[warp];
        for (int i = warp + WARPS * blockIdx.y; i < cnt; i += WARPS * SPLIT) {
            const float4 pi = p4[i];
            for (int j = lane; j < cntR; j += 32)
                kw[j] = makekey(pi, i, j);
            __syncwarp();
            {
                const int j0 = lane, j1 = lane + 32;
                const unsigned k0 = kw[j0];
                const unsigned k1 = (j1 < cntR) ? kw[j1] : 0xFFFFFFFFu;
                int r0 = 0, r1 = 0;
                #pragma unroll 4
                for (int kb = 0; kb < cntR; kb += 4) {
                    const uint4 q = *(const uint4*)&kw[kb];
                    r0 += (q.x < k0) + (q.y < k0) + (q.z < k0) + (q.w < k0);
                    r1 += (q.x < k1) + (q.y < k1) + (q.z < k1) + (q.w < k1);
                }
                if (r0 < KK) slotK[warp][r0] = k0;
                if (r1 < KK) slotK[warp][r1] = k1;
            }
            for (int jb = 64; jb < cnt; jb += 32) {
                const int j0 = jb + lane;
                const unsigned k0 = (j0 < cntR) ? kw[j0] : 0xFFFFFFFFu;
                int r0 = 0;
                #pragma unroll 4
                for (int kb = 0; kb < cntR; kb += 4) {
                    const uint4 q = *(const uint4*)&kw[kb];
                    r0 += (q.x < k0) + (q.y < k0) + (q.z < k0) + (q.w < k0);
                }
                if (r0 < KK) slotK[warp][r0] = k0;
            }
            __syncwarp();
            const int ig = start + i;
            const unsigned eb = (unsigned)ig * KK;
            float* p0 = out + eb;
            float* p1 = p0 + nK;
            float* p2 = p1 + nK;
            float* pr = out + 3u * nK + 5u * eb;
            const float figf = (float)ig;
            for (int s = lane; s < KK; s += 32)
                emit_slot(p0, p1, p2, pr, ig, figf, s, (s < v) ? slotK[warp][s] : 0u);
            __syncwarp();
        }
    }
}

extern "C" void kernel_launch(void* const* d_in, const int* in_sizes, int n_in,
                              void* d_out, int out_size)
{
    const float* pos    = (const float*)d_in[0];
    const int*   batchw = (const int*)d_in[1];
    float*       out    = (float*)d_out;
    bounds_kernel<<<NN / 256, 256>>>(batchw);
    dim3 grid(NG, SPLIT);
    knn_rdf_kernel<<<grid, 256>>>(pos, out);
}

// round 15
// speedup vs baseline: 1.0170x; 1.0170x over previous
#include <cuda_runtime.h>
#include <math.h>

#define NN 16384
#define NG 256
#define KK 50
#define NB 5
#define MAXC 192     // hard cap; counting fallback handles (128, 192]
#define WARPS 8
#define SPLIT 16
#define BIGD 1e10f

__device__ __forceinline__ float ex2_approx(float x) {
    float r; asm("ex2.approx.f32 %0, %1;" : "=f"(r) : "f"(x)); return r;
}
__device__ __forceinline__ float sqrt_approx(float x) {
    float r; asm("sqrt.approx.f32 %0, %1;" : "=f"(r) : "f"(x)); return r;
}

// one bitonic compare-exchange step (cross-lane, distance d)
__device__ __forceinline__ unsigned cmpex(unsigned k, int d, bool keep_min) {
    unsigned o = __shfl_xor_sync(0xFFFFFFFFu, k, d);
    unsigned mn = min(k, o), mx = max(k, o);
    return keep_min ? mn : mx;
}

__device__ __forceinline__ int bval(const int* bw, bool is64, int idx) {
    return bw[is64 ? 2 * idx : idx];
}

// warp-uniform full binary search fallback (probability ~0; correctness net)
__device__ __forceinline__ int lb_full(const int* bw, bool is64, int t) {
    int lo = 0, hi = NN;
    while (lo < hi) {
        int mid = (lo + hi) >> 1;
        if (bval(bw, is64, mid) < t) lo = mid + 1; else hi = mid;
    }
    return lo;
}

// Output layout (float32, out_size = 8*N*K):
//   [0,      nK)  : edge_index row 0 (src)
//   [nK,    2nK)  : edge_index row 1 (dst)
//   [2nK,   3nK)  : dist
//   [3nK,   8nK)  : rdf [nK,5] row-major
__global__ __launch_bounds__(256, 8) void knn_rdf_kernel(
    const float* __restrict__ pos,
    const int*   __restrict__ batch_w,   // raw words of batch (int32 or int64 layout)
    float*       __restrict__ out)
{
    __shared__ float4 p4[MAXC];                           // {x, y, z, |p|^2}
    __shared__ __align__(16) unsigned keys[WARPS][MAXC];  // fallback (cnt>128) only
    __shared__ unsigned slotK[WARPS][KK];                 // fallback only
    __shared__ int sB[2];

    const int g    = blockIdx.x;
    const int tid  = threadIdx.x;
    const int warp = tid >> 5, lane = tid & 31;

    // ---- warp-0 hint-window probe for lower_bound(g) and lower_bound(g+1) ----
    if (warp == 0) {
        const bool is64 = (batch_w[NN - 1] == 0);   // int64 layout: high word at odd idx
        const int hint = 64 * g;
        const int w0 = max(0, hint - 1024);
        const int w1 = min(NN, hint + 1024);
        // bracketing check: lb(g) >= w0  and  lb(g+1) <= w1
        bool ok = ((w0 == 0) || (bval(batch_w, is64, w0 - 1) < g)) &&
                  ((w1 == NN) || (bval(batch_w, is64, w1) > g));
        int sa, sb;
        if (ok) {
            // coarse: 32 samples at stride 64 cover the <=2048-wide window (one pass, two ballots)
            const int ci = w0 + lane * 64;
            const int cv = (ci < w1) ? bval(batch_w, is64, ci) : 0x7FFFFFFF;
            const int ca = __popc(__ballot_sync(0xFFFFFFFFu, cv < g));
            const int cb = __popc(__ballot_sync(0xFFFFFFFFu, cv < g + 1));
            // fine for target t given coarse count c
            auto fine = [&](int c, int t) -> int {
                if (c == 0) return w0;            // sample at w0 >= t and lb >= w0
                const int p = w0 + (c - 1) * 64;  // last coarse sample with val < t
                const int i0 = p + 1 + lane, i1 = i0 + 32;
                const int v0 = (i0 < NN) ? bval(batch_w, is64, i0) : 0x7FFFFFFF;
                const int v1 = (i1 < NN) ? bval(batch_w, is64, i1) : 0x7FFFFFFF;
                int cc = __popc(__ballot_sync(0xFFFFFFFFu, v0 < t))
                       + __popc(__ballot_sync(0xFFFFFFFFu, v1 < t));
                return p + 1 + cc;
            };
            sa = fine(ca, g);
            sb = fine(cb, g + 1);
        } else {
            sa = lb_full(batch_w, is64, g);
            sb = lb_full(batch_w, is64, g + 1);
        }
        if (lane == 0) { sB[0] = sa; sB[1] = sb; }
    }
    __syncthreads();
    const int start = sB[0];
    const int end   = sB[1];

    int cnt = end - start;
    if (cnt <= 0) return;
    if (cnt > MAXC) cnt = MAXC;   // safety clamp (never expected)
    // whole-block early exit: this block's warps own nodes [8*y, 8*y+8) (+ fallback strides)
    if (cnt <= 128 && WARPS * blockIdx.y >= cnt) return;
    const int cntR = (cnt + 3) & ~3;

    // stage this graph's positions + squared norms as float4
    for (int j = tid; j < cnt; j += blockDim.x) {
        float x = pos[3 * (start + j) + 0];
        float y = pos[3 * (start + j) + 1];
        float z = pos[3 * (start + j) + 2];
        p4[j] = make_float4(x, y, z, x * x + y * y + z * z);
    }
    __syncthreads();

    const unsigned nK = (unsigned)NN * KK;     // 819200, fits 32-bit
    const float EA = -0.11541560327111707f;    // -0.08 * log2(e)
    const float ET =  0.57707801635558534f;    //  0.40 * log2(e)
    const float C1 = 0.60653065971263342360f;
    const float C2 = 0.13533528323661270231f;
    const float C3 = 0.01110899653824230650f;
    const float C4 = 3.35462627902511838821e-4f;
    const float padDist = sqrtf(BIGD);

    const int v = min(cnt - 1, KK);            // valid (non-padding) slots per node

    // emit slot s using per-node precomputed pointers (p0..pr, ig, figf)
    auto emit_slot = [&](float* p0, float* p1, float* p2, float* pr,
                         int ig, float figf, int s, unsigned key) {
        float fsrc, dist, r0, r1, r2, r3, r4;
        if (s < v) {
            const int j = (int)(key & 0xFFu);
            unsigned ub = (key & 0xFFFFFF00u) | 0x80u;      // midpoint-restore low bits
            unsigned bits = (ub & 0x80000000u) ? (ub ^ 0x80000000u) : ~ub;
            const float d2 = __uint_as_float(bits);
            fsrc = (float)(start + j);
            dist = sqrt_approx(fmaxf(d2, 1e-12f));
            float A = ex2_approx(EA * dist * dist);
            float t = ex2_approx(ET * dist);
            r0 = A;
            float p = A * t; r1 = p * C1;
            p *= t;          r2 = p * C2;
            p *= t;          r3 = p * C3;
            p *= t;          r4 = p * C4;
        } else {
            int m = s - v;   // padding: masked indices ascending {0..start-1} ∪ {ig} ∪ {end..}
            int pidx = (m < start) ? m : ((m == start) ? ig : end + (m - start - 1));
            fsrc = (float)pidx;
            dist = padDist;
            r0 = r1 = r2 = r3 = r4 = 0.0f;
        }
        p0[s] = fsrc;
        p1[s] = figf;
        p2[s] = dist;
        float* rp = pr + 5 * s;
        rp[0] = r0; rp[1] = r1; rp[2] = r2; rp[3] = r3; rp[4] = r4;
    };

    // key from precomputed node record pi (one LDS.128 per candidate)
    auto makekey = [&](const float4 pi, int i, int j) -> unsigned {
        unsigned key = 0xFFFFFFFFu;
        if (j < cnt && j != i) {
            const float4 pj = p4[j];
            float d2 = pi.w + pj.w - 2.0f * (pi.x * pj.x + pi.y * pj.y + pi.z * pj.z);
            unsigned ub = __float_as_uint(d2);
            ub ^= ((unsigned)((int)ub >> 31)) | 0x80000000u;   // monotonic float->uint
            key = (ub & 0xFFFFFF00u) | (unsigned)j;
        }
        return key;
    };

    if (cnt <= 64) {
        // ---------- fast path A: 64-key register bitonic sort, one node per warp ----------
        const int i = warp + WARPS * blockIdx.y;
        if (i >= cnt) return;
        const float4 pi = p4[i];

        unsigned k0 = makekey(pi, i, lane);
        unsigned k1 = makekey(pi, i, lane + 32);

        #pragma unroll
        for (int s = 2; s <= 16; s <<= 1) {
            #pragma unroll
            for (int d = s >> 1; d >= 1; d >>= 1) {
                bool km = ((lane & d) == 0) == ((lane & s) == 0);
                k0 = cmpex(k0, d, km);
                k1 = cmpex(k1, d, km);
            }
        }
        #pragma unroll
        for (int d = 16; d >= 1; d >>= 1) {       // stage s=32
            bool pm = ((lane & d) == 0);
            k0 = cmpex(k0, d, pm);
            k1 = cmpex(k1, d, !pm);
        }
        { unsigned a = min(k0, k1), b = max(k0, k1); k0 = a; k1 = b; }  // s=64, d=32
        #pragma unroll
        for (int d = 16; d >= 1; d >>= 1) {
            bool pm = ((lane & d) == 0);
            k0 = cmpex(k0, d, pm);
            k1 = cmpex(k1, d, pm);
        }

        const int ig = start + i;
        const unsigned eb = (unsigned)ig * KK;
        float* p0 = out + eb;
        float* p1 = p0 + nK;
        float* p2 = p1 + nK;
        float* pr = out + 3u * nK + 5u * eb;
        const float figf = (float)ig;

        emit_slot(p0, p1, p2, pr, ig, figf, lane, k0);
        if (lane < KK - 32) emit_slot(p0, p1, p2, pr, ig, figf, lane + 32, k1);
    } else if (cnt <= 128) {
        // ---------- fast path B: bitonic top-64 of 128 keys, ONE node per warp ----------
        const int i = warp + WARPS * blockIdx.y;   // SPLIT=16 -> i in [0,128)
        if (i >= cnt) return;
        const float4 pi = p4[i];

        unsigned k0 = makekey(pi, i, lane);
        unsigned k1 = makekey(pi, i, lane + 32);
        unsigned k2 = makekey(pi, i, lane + 64);
        unsigned k3 = makekey(pi, i, lane + 96);

        #pragma unroll
        for (int s = 2; s <= 16; s <<= 1) {
            #pragma unroll
            for (int d = s >> 1; d >= 1; d >>= 1) {
                bool km = ((lane & d) == 0) == ((lane & s) == 0);
                k0 = cmpex(k0, d, km);
                k1 = cmpex(k1, d, km);
                k2 = cmpex(k2, d, km);
                k3 = cmpex(k3, d, km);
            }
        }
        #pragma unroll
        for (int d = 16; d >= 1; d >>= 1) {       // stage s=32
            bool pm = ((lane & d) == 0);
            k0 = cmpex(k0, d, pm);
            k1 = cmpex(k1, d, !pm);
            k2 = cmpex(k2, d, pm);
            k3 = cmpex(k3, d, !pm);
        }
        // stage s=64: (k0,k1) ascending 64-sort, (k2,k3) descending 64-sort
        { unsigned a = min(k0, k1), b = max(k0, k1); k0 = a; k1 = b; }
        { unsigned a = max(k2, k3), b = min(k2, k3); k2 = a; k3 = b; }
        #pragma unroll
        for (int d = 16; d >= 1; d >>= 1) {
            bool pm = ((lane & d) == 0);
            k0 = cmpex(k0, d, pm);
            k1 = cmpex(k1, d, pm);
            k2 = cmpex(k2, d, !pm);
            k3 = cmpex(k3, d, !pm);
        }
        // top-64 min-merge + 64-wide bitonic merge of (k0,k1)
        k0 = min(k0, k2);
        k1 = min(k1, k3);
        { unsigned a = min(k0, k1), b = max(k0, k1); k0 = a; k1 = b; }
        #pragma unroll
        for (int d = 16; d >= 1; d >>= 1) {
            bool pm = ((lane & d) == 0);
            k0 = cmpex(k0, d, pm);
            k1 = cmpex(k1, d, pm);
        }

        const int ig = start + i;
        const unsigned eb = (unsigned)ig * KK;
        float* p0 = out + eb;
        float* p1 = p0 + nK;
        float* p2 = p1 + nK;
        float* pr = out + 3u * nK + 5u * eb;
        const float figf = (float)ig;

        emit_slot(p0, p1, p2, pr, ig, figf, lane, k0);
        if (lane < KK - 32) emit_slot(p0, p1, p2, pr, ig, figf, lane + 32, k1);
    } else {
        // ---------- fallback (cnt>128, ~never): counting rank via smem keys ----------
        unsigned* kw = keys[warp];
        for (int i = warp + WARPS * blockIdx.y; i < cnt; i += WARPS * SPLIT) {
            const float4 pi = p4[i];
            for (int j = lane; j < cntR; j += 32)
                kw[j] = makekey(pi, i, j);
            __syncwarp();
            {
                const int j0 = lane, j1 = lane + 32;
                const unsigned k0 = kw[j0];
                const unsigned k1 = (j1 < cntR) ? kw[j1] : 0xFFFFFFFFu;
                int r0 = 0, r1 = 0;
                #pragma unroll 4
                for (int kb = 0; kb < cntR; kb += 4) {
                    const uint4 q = *(const uint4*)&kw[kb];
                    r0 += (q.x < k0) + (q.y < k0) + (q.z < k0) + (q.w < k0);
                    r1 += (q.x < k1) + (q.y < k1) + (q.z < k1) + (q.w < k1);
                }
                if (r0 < KK) slotK[warp][r0] = k0;
                if (r1 < KK) slotK[warp][r1] = k1;
            }
            for (int jb = 64; jb < cnt; jb += 32) {
                const int j0 = jb + lane;
                const unsigned k0 = (j0 < cntR) ? kw[j0] : 0xFFFFFFFFu;
                int r0 = 0;
                #pragma unroll 4
                for (int kb = 0; kb < cntR; kb += 4) {
                    const uint4 q = *(const uint4*)&kw[kb];
                    r0 += (q.x < k0) + (q.y < k0) + (q.z < k0) + (q.w < k0);
                }
                if (r0 < KK) slotK[warp][r0] = k0;
            }
            __syncwarp();
            const int ig = start + i;
            const unsigned eb = (unsigned)ig * KK;
            float* p0 = out + eb;
            float* p1 = p0 + nK;
            float* p2 = p1 + nK;
            float* pr = out + 3u * nK + 5u * eb;
            const float figf = (float)ig;
            for (int s = lane; s < KK; s += 32)
                emit_slot(p0, p1, p2, pr, ig, figf, s, (s < v) ? slotK[warp][s] : 0u);
            __syncwarp();
        }
    }
}

extern "C" void kernel_launch(void* const* d_in, const int* in_sizes, int n_in,
                              void* d_out, int out_size)
{
    const float* pos    = (const float*)d_in[0];
    const int*   batchw = (const int*)d_in[1];
    float*       out    = (float*)d_out;
    dim3 grid(NG, SPLIT);
    knn_rdf_kernel<<<grid, 256>>>(pos, batchw, out);
}